// round 3
// baseline (speedup 1.0000x reference)
#include <cuda_runtime.h>
#include <cstdint>

#define KS     5
#define K2     25
#define DYN    32
#define NB     4
#define NC     64
#define NH     256
#define NW     256
#define HW     (NH*NW)

#define TW     64
#define TH     8
#define PW     4
#define SW     68                 // cols w0-2 .. w0+65
#define SH     12                 // rows h0-2 .. h0+9
#define CHK    4                  // channels per chunk
#define F2_CH  (SH*(SW/2))        // 408 float2 per channel
#define F2_CK  (CHK*F2_CH)        // 1632 float2 per chunk
#define NSLOT  13                 // ceil(1632/128)
#define NTHR   128
#define NCHUNK 16
#define BUFS   3

__device__ __forceinline__ void cp_async8(uint32_t saddr, const float* gaddr, unsigned sz)
{
    asm volatile("cp.async.ca.shared.global [%0], [%1], 8, %2;\n"
                 :: "r"(saddr), "l"(gaddr), "r"(sz) : "memory");
}
__device__ __forceinline__ void cp_commit()
{
    asm volatile("cp.async.commit_group;\n" ::: "memory");
}
__device__ __forceinline__ float2 ffma2(float2 a, float2 b, float2 c)
{
    unsigned long long ua = *reinterpret_cast<unsigned long long*>(&a);
    unsigned long long ub = *reinterpret_cast<unsigned long long*>(&b);
    unsigned long long uc = *reinterpret_cast<unsigned long long*>(&c);
    unsigned long long ud;
    asm("fma.rn.f32x2 %0, %1, %2, %3;" : "=l"(ud) : "l"(ua), "l"(ub), "l"(uc));
    return *reinterpret_cast<float2*>(&ud);
}

__global__ __launch_bounds__(NTHR, 3)
void la_kernel(const float* __restrict__ x,
               const float* __restrict__ kern,
               float* __restrict__ out)
{
    __shared__ float2 smbuf[BUFS][F2_CK];   // 3 * 1632 * 8B = 39168 B
    __shared__ float  skw[K2];

    const int tid = threadIdx.x;
    const int tx  = tid & 15;
    const int ty  = tid >> 4;
    const int w0  = blockIdx.x * TW;
    const int h0  = blockIdx.y * TH;
    const int b   = blockIdx.z;
    const int ph  = h0 + ty;
    const int pw  = w0 + tx * PW;

    if (tid < K2) skw[tid] = kern[tid] * (1.0f / KS);

    // ---- chunk-invariant fill descriptors (8B granules) ----
    int goff[NSLOT];
    #pragma unroll
    for (int s = 0; s < NSLOT; ++s) {
        const int e   = tid + s * NTHR;
        const int ch  = e / F2_CH;
        const int rem = e - ch * F2_CH;
        const int r   = rem / (SW / 2);
        const int j   = rem - r * (SW / 2);
        const int gh  = h0 - 2 + r;
        const int gw0 = w0 - 2 + j * 2;
        const bool ok = ((unsigned)gh < NH) && ((unsigned)gw0 < NW);
        goff[s] = ok ? (ch * HW + gh * NW + gw0) : -1;
    }

    const float* xb = x + (long)b * NC * HW;

    // issue chunk 0 (static channels start at 32)
    {
        const float* g = xb + 32 * HW;
        const uint32_t sb = (uint32_t)__cvta_generic_to_shared(&smbuf[0][0]);
        #pragma unroll
        for (int s = 0; s < NSLOT; ++s) {
            const int e = tid + s * NTHR;
            if (s < NSLOT - 1 || e < F2_CK) {
                const int off = goff[s];
                cp_async8(sb + (uint32_t)e * 8u, g + (off >= 0 ? off : 0),
                          off >= 0 ? 8u : 0u);
            }
        }
        cp_commit();
    }

    // score pairs: sc01[k] = {score(p=0,k), score(p=1,k)}, sc23 likewise
    float2 sc01[K2], sc23[K2];
    #pragma unroll
    for (int k = 0; k < K2; ++k) { sc01[k] = make_float2(0.f, 0.f); sc23[k] = make_float2(0.f, 0.f); }

    float inv[PW];

    for (int i = 0; i < NCHUNK; ++i) {
        if (i + 1 < NCHUNK) {
            const int cb = (i + 1 < 8) ? (32 + 4 * (i + 1)) : (4 * (i + 1 - 8));
            const float* g = xb + cb * HW;
            const uint32_t sb = (uint32_t)__cvta_generic_to_shared(&smbuf[(i + 1) % BUFS][0]);
            #pragma unroll
            for (int s = 0; s < NSLOT; ++s) {
                const int e = tid + s * NTHR;
                if (s < NSLOT - 1 || e < F2_CK) {
                    const int off = goff[s];
                    cp_async8(sb + (uint32_t)e * 8u, g + (off >= 0 ? off : 0),
                              off >= 0 ? 8u : 0u);
                }
            }
            cp_commit();
            asm volatile("cp.async.wait_group 1;\n" ::: "memory");
        } else {
            asm volatile("cp.async.wait_group 0;\n" ::: "memory");
        }
        __syncthreads();

        const float* buf = (const float*)&smbuf[i % BUFS][0];

        if (i < 8) {
            // ================= Phase A: scores =================
            #pragma unroll
            for (int cc = 0; cc < CHK; ++cc) {
                const float* chb = buf + cc * (SH * SW);
                // center strip (row 2) -> also gives v pairs
                float2 vv01, vv23;
                {
                    const float4 A = *(const float4*)&chb[(ty + 2) * SW + 4 * tx];
                    const float4 B = *(const float4*)&chb[(ty + 2) * SW + 4 * tx + 4];
                    vv01 = make_float2(A.z, A.w);   // v0, v1
                    vv23 = make_float2(B.x, B.y);   // v2, v3
                    // row r=2 MACs
                    const float s0=A.x,s1=A.y,s2=A.z,s3=A.w,s4=B.x,s5=B.y,s6=B.z,s7=B.w;
                    float2 q[7] = { {s0,s1},{s1,s2},{s2,s3},{s3,s4},{s4,s5},{s5,s6},{s6,s7} };
                    #pragma unroll
                    for (int j = 0; j < KS; ++j) {
                        sc01[10 + j] = ffma2(q[j],     vv01, sc01[10 + j]);
                        sc23[10 + j] = ffma2(q[j + 2], vv23, sc23[10 + j]);
                    }
                }
                #pragma unroll
                for (int rr = 0; rr < 4; ++rr) {
                    const int r = (rr < 2) ? rr : rr + 1;   // 0,1,3,4
                    const float4 A = *(const float4*)&chb[(ty + r) * SW + 4 * tx];
                    const float4 B = *(const float4*)&chb[(ty + r) * SW + 4 * tx + 4];
                    const float s0=A.x,s1=A.y,s2=A.z,s3=A.w,s4=B.x,s5=B.y,s6=B.z,s7=B.w;
                    float2 q[7] = { {s0,s1},{s1,s2},{s2,s3},{s3,s4},{s4,s5},{s5,s6},{s6,s7} };
                    #pragma unroll
                    for (int j = 0; j < KS; ++j) {
                        sc01[r * KS + j] = ffma2(q[j],     vv01, sc01[r * KS + j]);
                        sc23[r * KS + j] = ffma2(q[j + 2], vv23, sc23[r * KS + j]);
                    }
                }
            }
            if (i == 7) {
                // ================= Phase B: softmax =================
                #pragma unroll
                for (int k = 0; k < K2; ++k) {
                    const float kw = skw[k];
                    sc01[k].x *= kw; sc01[k].y *= kw;
                    sc23[k].x *= kw; sc23[k].y *= kw;
                }
                float mx[PW] = {sc01[0].x, sc01[0].y, sc23[0].x, sc23[0].y};
                #pragma unroll
                for (int k = 1; k < K2; ++k) {
                    mx[0] = fmaxf(mx[0], sc01[k].x);
                    mx[1] = fmaxf(mx[1], sc01[k].y);
                    mx[2] = fmaxf(mx[2], sc23[k].x);
                    mx[3] = fmaxf(mx[3], sc23[k].y);
                }
                float sum[PW] = {0.f, 0.f, 0.f, 0.f};
                #pragma unroll
                for (int k = 0; k < K2; ++k) {
                    sc01[k].x = __expf(sc01[k].x - mx[0]); sum[0] += sc01[k].x;
                    sc01[k].y = __expf(sc01[k].y - mx[1]); sum[1] += sc01[k].y;
                    sc23[k].x = __expf(sc23[k].x - mx[2]); sum[2] += sc23[k].x;
                    sc23[k].y = __expf(sc23[k].y - mx[3]); sum[3] += sc23[k].y;
                }
                #pragma unroll
                for (int p = 0; p < PW; ++p) inv[p] = 1.0f / sum[p];
            }
        } else {
            // ================= Phase C: weighted sum =================
            #pragma unroll
            for (int cc = 0; cc < CHK; ++cc) {
                const float* chb = buf + cc * (SH * SW);
                float2 a01 = make_float2(0.f, 0.f), a23 = make_float2(0.f, 0.f);
                #pragma unroll
                for (int r = 0; r < KS; ++r) {
                    const float4 A = *(const float4*)&chb[(ty + r) * SW + 4 * tx];
                    const float4 B = *(const float4*)&chb[(ty + r) * SW + 4 * tx + 4];
                    const float s0=A.x,s1=A.y,s2=A.z,s3=A.w,s4=B.x,s5=B.y,s6=B.z,s7=B.w;
                    float2 q[7] = { {s0,s1},{s1,s2},{s2,s3},{s3,s4},{s4,s5},{s5,s6},{s6,s7} };
                    #pragma unroll
                    for (int j = 0; j < KS; ++j) {
                        a01 = ffma2(sc01[r * KS + j], q[j],     a01);
                        a23 = ffma2(sc23[r * KS + j], q[j + 2], a23);
                    }
                }
                const int c = (i - 8) * CHK + cc;
                float4 o;
                o.x = a01.x * inv[0];
                o.y = a01.y * inv[1];
                o.z = a23.x * inv[2];
                o.w = a23.y * inv[3];
                *(float4*)&out[(((long)b * DYN + c) * NH + ph) * NW + pw] = o;
            }
        }
    }
}

extern "C" void kernel_launch(void* const* d_in, const int* in_sizes, int n_in,
                              void* d_out, int out_size)
{
    const float* x    = (const float*)d_in[0];
    const float* kern = (const float*)d_in[1];
    float* out        = (float*)d_out;
    (void)in_sizes; (void)n_in; (void)out_size;

    dim3 grid(NW / TW, NH / TH, NB);   // (4, 32, 4) = 512 blocks
    dim3 block(NTHR);
    la_kernel<<<grid, block>>>(x, kern, out);
}

// round 4
// speedup vs baseline: 1.1037x; 1.1037x over previous
#include <cuda_runtime.h>
#include <cstdint>

#define KS     5
#define K2     25
#define DYN    32
#define NB     4
#define NC     64
#define NH     256
#define NW     256
#define HW     (NH*NW)

#define TW     64
#define TH     8
#define PW     4
#define SW     72                 // cols w0-4 .. w0+67 (16B-aligned origin)
#define SH     12                 // rows h0-2 .. h0+9
#define CHK    4                  // channels per chunk
#define F4_CH  (SH*(SW/4))        // 216 float4 per channel
#define F4_CK  (CHK*F4_CH)        // 864 float4 per chunk
#define NSLOT  7                  // ceil(864/128)
#define NTHR   128
#define NCHUNK 16                 // 8 static + 8 dynamic
#define BUFS   3

__device__ __forceinline__ void cp_async16(uint32_t saddr, const float* gaddr, unsigned sz)
{
    asm volatile("cp.async.cg.shared.global [%0], [%1], 16, %2;\n"
                 :: "r"(saddr), "l"(gaddr), "r"(sz) : "memory");
}
__device__ __forceinline__ void cp_commit()
{
    asm volatile("cp.async.commit_group;\n" ::: "memory");
}

__global__ __launch_bounds__(NTHR, 3)
void la_kernel(const float* __restrict__ x,
               const float* __restrict__ kern,
               float* __restrict__ out)
{
    __shared__ float4 smbuf[BUFS][F4_CK];   // 3 * 864 * 16B = 40.5 KB
    __shared__ float  skw[K2];

    const int tid = threadIdx.x;
    const int tx  = tid & 15;
    const int ty  = tid >> 4;
    const int w0  = blockIdx.x * TW;
    const int h0  = blockIdx.y * TH;
    const int b   = blockIdx.z;
    const int ph  = h0 + ty;
    const int pw  = w0 + tx * PW;

    if (tid < K2) skw[tid] = kern[tid] * (1.0f / KS);

    // ---- chunk-invariant fill descriptors (16B granules) ----
    int goff[NSLOT];
    #pragma unroll
    for (int s = 0; s < NSLOT; ++s) {
        const int e   = tid + s * NTHR;
        const int ch  = e / F4_CH;
        const int rem = e - ch * F4_CH;
        const int r   = rem / (SW / 4);
        const int j   = rem - r * (SW / 4);
        const int gh  = h0 - 2 + r;
        const int gw0 = w0 - 4 + j * 4;
        const bool ok = ((unsigned)gh < NH) && ((unsigned)gw0 < NW);
        goff[s] = ok ? (ch * HW + gh * NW + gw0) : -1;
    }

    const float* xb = x + (long)b * NC * HW;

    // issue chunk 0 (static channels start at 32)
    {
        const float* g = xb + 32 * HW;
        const uint32_t sb = (uint32_t)__cvta_generic_to_shared(&smbuf[0][0]);
        #pragma unroll
        for (int s = 0; s < NSLOT; ++s) {
            const int e = tid + s * NTHR;
            if (s < NSLOT - 1 || e < F4_CK) {
                const int off = goff[s];
                cp_async16(sb + (uint32_t)e * 16u, g + (off >= 0 ? off : 0),
                           off >= 0 ? 16u : 0u);
            }
        }
        cp_commit();
    }

    float sc[PW][K2];
    #pragma unroll
    for (int p = 0; p < PW; ++p)
        #pragma unroll
        for (int k = 0; k < K2; ++k) sc[p][k] = 0.0f;

    float inv[PW];

    for (int i = 0; i < NCHUNK; ++i) {
        if (i + 1 < NCHUNK) {
            const int cb = (i + 1 < 8) ? (32 + 4 * (i + 1)) : (4 * (i + 1 - 8));
            const float* g = xb + cb * HW;
            const uint32_t sb = (uint32_t)__cvta_generic_to_shared(&smbuf[(i + 1) % BUFS][0]);
            #pragma unroll
            for (int s = 0; s < NSLOT; ++s) {
                const int e = tid + s * NTHR;
                if (s < NSLOT - 1 || e < F4_CK) {
                    const int off = goff[s];
                    cp_async16(sb + (uint32_t)e * 16u, g + (off >= 0 ? off : 0),
                               off >= 0 ? 16u : 0u);
                }
            }
            cp_commit();
            asm volatile("cp.async.wait_group 1;\n" ::: "memory");
        } else {
            asm volatile("cp.async.wait_group 0;\n" ::: "memory");
        }
        __syncthreads();

        const float* buf = (const float*)&smbuf[i % BUFS][0];

        if (i < 8) {
            // ================= Phase A: scores =================
            #pragma unroll
            for (int cc = 0; cc < CHK; ++cc) {
                const float* chb = buf + cc * (SH * SW) + ty * SW + tx * 4;
                // row r=2 first: strip gives both taps and center values
                float v[PW];
                {
                    const float2 e0 = *(const float2*)(chb + 2 * SW + 2);
                    const float4 Bq = *(const float4*)(chb + 2 * SW + 4);
                    const float2 e1 = *(const float2*)(chb + 2 * SW + 8);
                    v[0] = Bq.x; v[1] = Bq.y; v[2] = Bq.z; v[3] = Bq.w;
                    const float s[8] = {e0.x, e0.y, Bq.x, Bq.y, Bq.z, Bq.w, e1.x, e1.y};
                    #pragma unroll
                    for (int j = 0; j < KS; ++j)
                        #pragma unroll
                        for (int p = 0; p < PW; ++p)
                            sc[p][10 + j] = fmaf(s[j + p], v[p], sc[p][10 + j]);
                }
                #pragma unroll
                for (int rr = 0; rr < 4; ++rr) {
                    const int r = (rr < 2) ? rr : rr + 1;   // 0,1,3,4
                    const float2 e0 = *(const float2*)(chb + r * SW + 2);
                    const float4 Bq = *(const float4*)(chb + r * SW + 4);
                    const float2 e1 = *(const float2*)(chb + r * SW + 8);
                    const float s[8] = {e0.x, e0.y, Bq.x, Bq.y, Bq.z, Bq.w, e1.x, e1.y};
                    #pragma unroll
                    for (int j = 0; j < KS; ++j)
                        #pragma unroll
                        for (int p = 0; p < PW; ++p)
                            sc[p][r * KS + j] = fmaf(s[j + p], v[p], sc[p][r * KS + j]);
                }
            }
            if (i == 7) {
                // ================= Phase B: softmax =================
                #pragma unroll
                for (int k = 0; k < K2; ++k) {
                    const float kw = skw[k];
                    #pragma unroll
                    for (int p = 0; p < PW; ++p) sc[p][k] *= kw;
                }
                #pragma unroll
                for (int p = 0; p < PW; ++p) {
                    float mx = sc[p][0];
                    #pragma unroll
                    for (int k = 1; k < K2; ++k) mx = fmaxf(mx, sc[p][k]);
                    float sum = 0.0f;
                    #pragma unroll
                    for (int k = 0; k < K2; ++k) {
                        const float e = __expf(sc[p][k] - mx);
                        sc[p][k] = e;
                        sum += e;
                    }
                    inv[p] = 1.0f / sum;
                }
            }
        } else {
            // ================= Phase C: weighted sum =================
            #pragma unroll
            for (int cc = 0; cc < CHK; ++cc) {
                const float* chb = buf + cc * (SH * SW) + ty * SW + tx * 4;
                float acc[PW] = {0.f, 0.f, 0.f, 0.f};
                #pragma unroll
                for (int r = 0; r < KS; ++r) {
                    const float2 e0 = *(const float2*)(chb + r * SW + 2);
                    const float4 Bq = *(const float4*)(chb + r * SW + 4);
                    const float2 e1 = *(const float2*)(chb + r * SW + 8);
                    const float s[8] = {e0.x, e0.y, Bq.x, Bq.y, Bq.z, Bq.w, e1.x, e1.y};
                    #pragma unroll
                    for (int j = 0; j < KS; ++j)
                        #pragma unroll
                        for (int p = 0; p < PW; ++p)
                            acc[p] = fmaf(sc[p][r * KS + j], s[j + p], acc[p]);
                }
                const int c = (i - 8) * CHK + cc;
                float4 o;
                o.x = acc[0] * inv[0];
                o.y = acc[1] * inv[1];
                o.z = acc[2] * inv[2];
                o.w = acc[3] * inv[3];
                *(float4*)&out[(((long)b * DYN + c) * NH + ph) * NW + pw] = o;
            }
        }
    }
}

extern "C" void kernel_launch(void* const* d_in, const int* in_sizes, int n_in,
                              void* d_out, int out_size)
{
    const float* x    = (const float*)d_in[0];
    const float* kern = (const float*)d_in[1];
    float* out        = (float*)d_out;
    (void)in_sizes; (void)n_in; (void)out_size;

    dim3 grid(NW / TW, NH / TH, NB);   // (4, 32, 4) = 512 blocks
    dim3 block(NTHR);
    la_kernel<<<grid, block>>>(x, kern, out);
}

// round 5
// speedup vs baseline: 1.3249x; 1.2004x over previous
#include <cuda_runtime.h>
#include <cstdint>

#define KS     5
#define K2     25
#define DYN    32
#define NB     4
#define NC     64
#define NH     256
#define NW     256
#define HW     (NH*NW)

#define TW     64
#define TH     8
#define PW     4
#define SW     72                 // cols w0-4 .. w0+67 (16B-aligned origin)
#define SH     12                 // rows h0-2 .. h0+9
#define CHK    4                  // channels per chunk
#define F4_CH  (SH*(SW/4))        // 216 float4 per channel
#define F4_CK  (CHK*F4_CH)        // 864 float4 per chunk
#define NSLOT  7                  // ceil(864/128)
#define NTHR   128
#define NCHUNK 16                 // 8 static + 8 dynamic
#define BUFS   3

__device__ __forceinline__ void cp_async16(uint32_t saddr, const float* gaddr, unsigned sz)
{
    asm volatile("cp.async.cg.shared.global [%0], [%1], 16, %2;\n"
                 :: "r"(saddr), "l"(gaddr), "r"(sz) : "memory");
}
__device__ __forceinline__ void cp_commit()
{
    asm volatile("cp.async.commit_group;\n" ::: "memory");
}

__global__ __launch_bounds__(NTHR, 4)
void la_kernel(const float* __restrict__ x,
               const float* __restrict__ kern,
               float* __restrict__ out)
{
    __shared__ float4 smbuf[BUFS][F4_CK];     // 40.5 KB
    __shared__ int    sgoff[NSLOT][NTHR];     // 3.5 KB fill descriptors
    __shared__ float  skw[K2];

    const int tid = threadIdx.x;
    const int tx  = tid & 15;
    const int ty  = tid >> 4;
    const int w0  = blockIdx.x * TW;
    const int h0  = blockIdx.y * TH;
    const int b   = blockIdx.z;
    const int ph  = h0 + ty;
    const int pw  = w0 + tx * PW;

    if (tid < K2) skw[tid] = kern[tid] * (1.0f / KS);

    // ---- chunk-invariant fill descriptors, stored in smem ----
    #pragma unroll
    for (int s = 0; s < NSLOT; ++s) {
        const int e   = tid + s * NTHR;
        const int ch  = e / F4_CH;
        const int rem = e - ch * F4_CH;
        const int r   = rem / (SW / 4);
        const int j   = rem - r * (SW / 4);
        const int gh  = h0 - 2 + r;
        const int gw0 = w0 - 4 + j * 4;
        const bool ok = ((unsigned)gh < NH) && ((unsigned)gw0 < NW);
        sgoff[s][tid] = ok ? (ch * HW + gh * NW + gw0) : -1;
    }
    __syncthreads();

    const float* xb = x + (long)b * NC * HW;

    // issue chunk 0 (static channels start at 32)
    {
        const float* g = xb + 32 * HW;
        const uint32_t sb = (uint32_t)__cvta_generic_to_shared(&smbuf[0][0]);
        #pragma unroll
        for (int s = 0; s < NSLOT; ++s) {
            const int e = tid + s * NTHR;
            if (s < NSLOT - 1 || e < F4_CK) {
                const int off = sgoff[s][tid];
                cp_async16(sb + (uint32_t)e * 16u, g + (off >= 0 ? off : 0),
                           off >= 0 ? 16u : 0u);
            }
        }
        cp_commit();
    }

    float sc[PW][K2];
    #pragma unroll
    for (int p = 0; p < PW; ++p)
        #pragma unroll
        for (int k = 0; k < K2; ++k) sc[p][k] = 0.0f;

    float inv[PW];

    for (int i = 0; i < NCHUNK; ++i) {
        if (i + 1 < NCHUNK) {
            const int cb = (i + 1 < 8) ? (32 + 4 * (i + 1)) : (4 * (i + 1 - 8));
            const float* g = xb + cb * HW;
            const uint32_t sb = (uint32_t)__cvta_generic_to_shared(&smbuf[(i + 1) % BUFS][0]);
            #pragma unroll
            for (int s = 0; s < NSLOT; ++s) {
                const int e = tid + s * NTHR;
                if (s < NSLOT - 1 || e < F4_CK) {
                    const int off = sgoff[s][tid];
                    cp_async16(sb + (uint32_t)e * 16u, g + (off >= 0 ? off : 0),
                               off >= 0 ? 16u : 0u);
                }
            }
            cp_commit();
            asm volatile("cp.async.wait_group 1;\n" ::: "memory");
        } else {
            asm volatile("cp.async.wait_group 0;\n" ::: "memory");
        }
        __syncthreads();

        const float* buf = (const float*)&smbuf[i % BUFS][0];

        if (i < 8) {
            // ================= Phase A: scores =================
            #pragma unroll
            for (int cc = 0; cc < CHK; ++cc) {
                const float* chb = buf + cc * (SH * SW);
                float v[PW];
                {
                    const float2 cA = *(const float2*)&chb[(ty + 2) * SW + tx * 4 + 4];
                    const float2 cB = *(const float2*)&chb[(ty + 2) * SW + tx * 4 + 6];
                    v[0] = cA.x; v[1] = cA.y; v[2] = cB.x; v[3] = cB.y;
                }
                #pragma unroll
                for (int r = 0; r < KS; ++r) {
                    const float* rp = &chb[(ty + r) * SW + tx * 4];
                    const float4 a = *(const float4*)(rp);
                    const float4 m = *(const float4*)(rp + 4);
                    const float4 c = *(const float4*)(rp + 8);
                    const float s[12] = {a.x, a.y, a.z, a.w, m.x, m.y, m.z, m.w,
                                         c.x, c.y, c.z, c.w};
                    #pragma unroll
                    for (int j = 0; j < KS; ++j)
                        #pragma unroll
                        for (int p = 0; p < PW; ++p)
                            sc[p][r * KS + j] = fmaf(s[2 + j + p], v[p], sc[p][r * KS + j]);
                }
            }
            if (i == 7) {
                // ================= Phase B: softmax =================
                #pragma unroll
                for (int k = 0; k < K2; ++k) {
                    const float kw = skw[k];
                    #pragma unroll
                    for (int p = 0; p < PW; ++p) sc[p][k] *= kw;
                }
                #pragma unroll
                for (int p = 0; p < PW; ++p) {
                    float mx = sc[p][0];
                    #pragma unroll
                    for (int k = 1; k < K2; ++k) mx = fmaxf(mx, sc[p][k]);
                    float sum = 0.0f;
                    #pragma unroll
                    for (int k = 0; k < K2; ++k) {
                        const float e = __expf(sc[p][k] - mx);
                        sc[p][k] = e;
                        sum += e;
                    }
                    inv[p] = 1.0f / sum;
                }
            }
        } else {
            // ================= Phase C: weighted sum =================
            #pragma unroll
            for (int cc = 0; cc < CHK; ++cc) {
                const float* chb = buf + cc * (SH * SW);
                float acc[PW] = {0.f, 0.f, 0.f, 0.f};
                #pragma unroll
                for (int r = 0; r < KS; ++r) {
                    const float* rp = &chb[(ty + r) * SW + tx * 4];
                    const float4 a = *(const float4*)(rp);
                    const float4 m = *(const float4*)(rp + 4);
                    const float4 c = *(const float4*)(rp + 8);
                    const float s[12] = {a.x, a.y, a.z, a.w, m.x, m.y, m.z, m.w,
                                         c.x, c.y, c.z, c.w};
                    #pragma unroll
                    for (int j = 0; j < KS; ++j)
                        #pragma unroll
                        for (int p = 0; p < PW; ++p)
                            acc[p] = fmaf(sc[p][r * KS + j], s[2 + j + p], acc[p]);
                }
                const int c = (i - 8) * CHK + cc;
                float4 o;
                o.x = acc[0] * inv[0];
                o.y = acc[1] * inv[1];
                o.z = acc[2] * inv[2];
                o.w = acc[3] * inv[3];
                *(float4*)&out[(((long)b * DYN + c) * NH + ph) * NW + pw] = o;
            }
        }
    }
}

extern "C" void kernel_launch(void* const* d_in, const int* in_sizes, int n_in,
                              void* d_out, int out_size)
{
    const float* x    = (const float*)d_in[0];
    const float* kern = (const float*)d_in[1];
    float* out        = (float*)d_out;
    (void)in_sizes; (void)n_in; (void)out_size;

    dim3 grid(NW / TW, NH / TH, NB);   // (4, 32, 4) = 512 blocks
    dim3 block(NTHR);
    la_kernel<<<grid, block>>>(x, kern, out);
}

// round 9
// speedup vs baseline: 1.4391x; 1.0862x over previous
#include <cuda_runtime.h>
#include <cstdint>

#define KS     5
#define K2     25
#define DYN    32
#define NB     4
#define NC     64
#define NH     256
#define NW     256
#define HW     (NH*NW)

#define TW     64
#define TH     8
#define PW     4
#define SW     68                 // tile cols w0 .. w0+67 (origin w0, 16B aligned)
#define SH     12                 // rows h0-2 .. h0+9
#define CHK    4                  // channels per chunk
#define F4_CH  (SH*(SW/4))        // 204 float4 per channel
#define F4_CK  (CHK*F4_CH)        // 816 float4 per chunk
#define NSLOT  7                  // ceil(816/128)
#define NTHR   128
#define NCHUNK 16                 // 8 static + 8 dynamic
#define BUFS   3

__device__ __forceinline__ void cp_async16(uint32_t saddr, const float* gaddr, unsigned sz)
{
    asm volatile("cp.async.cg.shared.global [%0], [%1], 16, %2;\n"
                 :: "r"(saddr), "l"(gaddr), "r"(sz) : "memory");
}
__device__ __forceinline__ void cp_commit()
{
    asm volatile("cp.async.commit_group;\n" ::: "memory");
}

__global__ __launch_bounds__(NTHR, 4)
void la_kernel(const float* __restrict__ x,
               const float* __restrict__ kern,
               float* __restrict__ out)
{
    // ===================== EDGE BLOCKS (by == 32): pixels col 0,1 =====================
    if (blockIdx.y == 32) {
        const int tid = threadIdx.x;
        const int b   = blockIdx.z;
        const int R   = blockIdx.x * 64 + (tid >> 1);   // row 0..255
        const int col = tid & 1;                         // 0 or 1
        const float* xb = x + (long)b * NC * HW;

        float sc[K2];
        #pragma unroll
        for (int k = 0; k < K2; ++k) sc[k] = 0.0f;

        for (int ch = DYN; ch < NC; ++ch) {
            const float* cp = xb + ch * HW;
            float4 rowv[KS];
            #pragma unroll
            for (int i = 0; i < KS; ++i) {
                const int gr = R - 2 + i;
                rowv[i] = ((unsigned)gr < NH) ? *(const float4*)(cp + gr * NW)
                                              : make_float4(0.f, 0.f, 0.f, 0.f);
            }
            const float v = (col == 0) ? rowv[2].x : rowv[2].y;
            #pragma unroll
            for (int i = 0; i < KS; ++i) {
                if (col == 0) {
                    sc[i * KS + 2] = fmaf(rowv[i].x, v, sc[i * KS + 2]);
                    sc[i * KS + 3] = fmaf(rowv[i].y, v, sc[i * KS + 3]);
                    sc[i * KS + 4] = fmaf(rowv[i].z, v, sc[i * KS + 4]);
                } else {
                    sc[i * KS + 1] = fmaf(rowv[i].x, v, sc[i * KS + 1]);
                    sc[i * KS + 2] = fmaf(rowv[i].y, v, sc[i * KS + 2]);
                    sc[i * KS + 3] = fmaf(rowv[i].z, v, sc[i * KS + 3]);
                    sc[i * KS + 4] = fmaf(rowv[i].w, v, sc[i * KS + 4]);
                }
            }
        }
        // softmax (taps off the left edge keep score 0, matching zero padding)
        float mx = sc[0];
        #pragma unroll
        for (int k = 1; k < K2; ++k) mx = fmaxf(mx, sc[k] * (__ldg(kern + k) * 0.2f));
        mx = fmaxf(mx, sc[0] * (__ldg(kern + 0) * 0.2f));
        mx = 0.0f;  // recompute cleanly below
        {
            float tmp[K2];
            #pragma unroll
            for (int k = 0; k < K2; ++k) tmp[k] = sc[k] * (__ldg(kern + k) * 0.2f);
            float m2 = tmp[0];
            #pragma unroll
            for (int k = 1; k < K2; ++k) m2 = fmaxf(m2, tmp[k]);
            float sum = 0.0f;
            #pragma unroll
            for (int k = 0; k < K2; ++k) { tmp[k] = __expf(tmp[k] - m2); sum += tmp[k]; }
            const float inv = 1.0f / sum;
            #pragma unroll
            for (int k = 0; k < K2; ++k) sc[k] = tmp[k] * inv;
        }
        // weighted sum over dynamic channels
        for (int ch = 0; ch < DYN; ++ch) {
            const float* cp = xb + ch * HW;
            float acc = 0.0f;
            #pragma unroll
            for (int i = 0; i < KS; ++i) {
                const int gr = R - 2 + i;
                const float4 rv = ((unsigned)gr < NH) ? *(const float4*)(cp + gr * NW)
                                                      : make_float4(0.f, 0.f, 0.f, 0.f);
                if (col == 0) {
                    acc = fmaf(sc[i * KS + 2], rv.x, acc);
                    acc = fmaf(sc[i * KS + 3], rv.y, acc);
                    acc = fmaf(sc[i * KS + 4], rv.z, acc);
                } else {
                    acc = fmaf(sc[i * KS + 1], rv.x, acc);
                    acc = fmaf(sc[i * KS + 2], rv.y, acc);
                    acc = fmaf(sc[i * KS + 3], rv.z, acc);
                    acc = fmaf(sc[i * KS + 4], rv.w, acc);
                }
            }
            out[((long)(b * DYN + ch) * NH + R) * NW + col] = acc;
        }
        return;
    }

    // ===================== MAIN BLOCKS =====================
    __shared__ float4 smbuf[BUFS][F4_CK];     // 3*816*16B = 38.25 KB
    __shared__ int    sgoff[NSLOT][NTHR];     // 3.5 KB fill descriptors
    __shared__ float  skw[K2];

    const int tid = threadIdx.x;
    const int tx  = tid & 15;
    const int ty  = tid >> 4;
    const int w0  = blockIdx.x * TW;
    const int h0  = blockIdx.y * TH;
    const int b   = blockIdx.z;
    const int ph  = h0 + ty;
    const int p0  = w0 + 2 + tx * PW;         // first owned pixel (shifted by +2)

    if (tid < K2) skw[tid] = kern[tid] * (1.0f / KS);

    // ---- chunk-invariant fill descriptors (16B granules), tile origin (w0, h0-2) ----
    #pragma unroll
    for (int s = 0; s < NSLOT; ++s) {
        const int e   = tid + s * NTHR;
        const int ch  = e / F4_CH;
        const int rem = e - ch * F4_CH;
        const int r   = rem / (SW / 4);
        const int j   = rem - r * (SW / 4);
        const int gh  = h0 - 2 + r;
        const int gw0 = w0 + j * 4;
        const bool ok = ((unsigned)gh < NH) && ((unsigned)gw0 < NW);
        sgoff[s][tid] = ok ? (ch * HW + gh * NW + gw0) : -1;
    }
    __syncthreads();

    const float* xb = x + (long)b * NC * HW;

    // issue chunk 0 (static channels start at 32)
    {
        const float* g = xb + 32 * HW;
        const uint32_t sb = (uint32_t)__cvta_generic_to_shared(&smbuf[0][0]);
        #pragma unroll
        for (int s = 0; s < NSLOT; ++s) {
            const int e = tid + s * NTHR;
            if (s < NSLOT - 1 || e < F4_CK) {
                const int off = sgoff[s][tid];
                cp_async16(sb + (uint32_t)e * 16u, g + (off >= 0 ? off : 0),
                           off >= 0 ? 16u : 0u);
            }
        }
        cp_commit();
    }

    float sc[PW][K2];
    #pragma unroll
    for (int p = 0; p < PW; ++p)
        #pragma unroll
        for (int k = 0; k < K2; ++k) sc[p][k] = 0.0f;

    float inv[PW];

    for (int i = 0; i < NCHUNK; ++i) {
        if (i + 1 < NCHUNK) {
            const int cb = (i + 1 < 8) ? (32 + 4 * (i + 1)) : (4 * (i + 1 - 8));
            const float* g = xb + cb * HW;
            const uint32_t sb = (uint32_t)__cvta_generic_to_shared(&smbuf[(i + 1) % BUFS][0]);
            #pragma unroll
            for (int s = 0; s < NSLOT; ++s) {
                const int e = tid + s * NTHR;
                if (s < NSLOT - 1 || e < F4_CK) {
                    const int off = sgoff[s][tid];
                    cp_async16(sb + (uint32_t)e * 16u, g + (off >= 0 ? off : 0),
                               off >= 0 ? 16u : 0u);
                }
            }
            cp_commit();
            asm volatile("cp.async.wait_group 1;\n" ::: "memory");
        } else {
            asm volatile("cp.async.wait_group 0;\n" ::: "memory");
        }
        __syncthreads();

        const float* buf = (const float*)&smbuf[i % BUFS][0];

        if (i < 8) {
            // ================= Phase A: scores =================
            #pragma unroll
            for (int cc = 0; cc < CHK; ++cc) {
                const float* chb = buf + cc * (SH * SW) + ty * SW + tx * 4;
                float v[PW];
                {   // row r=2: strip supplies taps AND the 4 center values (s[2+p])
                    const float4 A = *(const float4*)(chb + 2 * SW);
                    const float4 B = *(const float4*)(chb + 2 * SW + 4);
                    v[0] = A.z; v[1] = A.w; v[2] = B.x; v[3] = B.y;
                    const float s[8] = {A.x, A.y, A.z, A.w, B.x, B.y, B.z, B.w};
                    #pragma unroll
                    for (int j = 0; j < KS; ++j)
                        #pragma unroll
                        for (int p = 0; p < PW; ++p)
                            sc[p][10 + j] = fmaf(s[j + p], v[p], sc[p][10 + j]);
                }
                #pragma unroll
                for (int rr = 0; rr < 4; ++rr) {
                    const int r = (rr < 2) ? rr : rr + 1;   // 0,1,3,4
                    const float4 A = *(const float4*)(chb + r * SW);
                    const float4 B = *(const float4*)(chb + r * SW + 4);
                    const float s[8] = {A.x, A.y, A.z, A.w, B.x, B.y, B.z, B.w};
                    #pragma unroll
                    for (int j = 0; j < KS; ++j)
                        #pragma unroll
                        for (int p = 0; p < PW; ++p)
                            sc[p][r * KS + j] = fmaf(s[j + p], v[p], sc[p][r * KS + j]);
                }
            }
            if (i == 7) {
                // ================= Phase B: softmax =================
                #pragma unroll
                for (int k = 0; k < K2; ++k) {
                    const float kw = skw[k];
                    #pragma unroll
                    for (int p = 0; p < PW; ++p) sc[p][k] *= kw;
                }
                #pragma unroll
                for (int p = 0; p < PW; ++p) {
                    float mx = sc[p][0];
                    #pragma unroll
                    for (int k = 1; k < K2; ++k) mx = fmaxf(mx, sc[p][k]);
                    float sum = 0.0f;
                    #pragma unroll
                    for (int k = 0; k < K2; ++k) {
                        const float e = __expf(sc[p][k] - mx);
                        sc[p][k] = e;
                        sum += e;
                    }
                    inv[p] = 1.0f / sum;
                }
            }
        } else {
            // ================= Phase C: weighted sum =================
            #pragma unroll
            for (int cc = 0; cc < CHK; ++cc) {
                const float* chb = buf + cc * (SH * SW) + ty * SW + tx * 4;
                float acc[PW] = {0.f, 0.f, 0.f, 0.f};
                #pragma unroll
                for (int r = 0; r < KS; ++r) {
                    const float4 A = *(const float4*)(chb + r * SW);
                    const float4 B = *(const float4*)(chb + r * SW + 4);
                    const float s[8] = {A.x, A.y, A.z, A.w, B.x, B.y, B.z, B.w};
                    #pragma unroll
                    for (int j = 0; j < KS; ++j)
                        #pragma unroll
                        for (int p = 0; p < PW; ++p)
                            acc[p] = fmaf(sc[p][r * KS + j], s[j + p], acc[p]);
                }
                const int c = (i - 8) * CHK + cc;
                float* op = &out[(((long)b * DYN + c) * NH + ph) * NW + p0];
                float2 o0 = make_float2(acc[0] * inv[0], acc[1] * inv[1]);
                *(float2*)op = o0;                       // pixels p0, p0+1 (always valid)
                if (p0 + 2 < NW) {                        // masked for bx=3, tx=15
                    float2 o1 = make_float2(acc[2] * inv[2], acc[3] * inv[3]);
                    *(float2*)(op + 2) = o1;
                }
            }
        }
    }
}

extern "C" void kernel_launch(void* const* d_in, const int* in_sizes, int n_in,
                              void* d_out, int out_size)
{
    const float* x    = (const float*)d_in[0];
    const float* kern = (const float*)d_in[1];
    float* out        = (float*)d_out;
    (void)in_sizes; (void)n_in; (void)out_size;

    dim3 grid(NW / TW, NH / TH + 1, NB);   // (4, 33, 4): by==32 -> edge blocks
    dim3 block(NTHR);
    la_kernel<<<grid, block>>>(x, kern, out);
}

// round 10
// speedup vs baseline: 1.4934x; 1.0378x over previous
#include <cuda_runtime.h>
#include <cstdint>

#define KS     5
#define K2     25
#define DYN    32
#define NB     4
#define NC     64
#define NH     256
#define NW     256
#define HW     (NH*NW)

#define TW     64
#define TH     8
#define PW     4
#define SW     68                 // tile cols w0 .. w0+67 (origin w0, 16B aligned)
#define SH     12                 // rows h0-2 .. h0+9
#define CHK    4                  // channels per chunk
#define F4_CH  (SH*(SW/4))        // 204 float4 per channel
#define F4_CK  (CHK*F4_CH)        // 816 float4 per chunk
#define NSLOT  7                  // ceil(816/128)
#define NTHR   128
#define NCHUNK 16                 // 8 static + 8 dynamic
#define BUFS   4                  // prefetch distance 2

#define SMEM_BYTES (BUFS*F4_CK*16 + NSLOT*NTHR*4 + K2*4)

__device__ __forceinline__ void cp_async16(uint32_t saddr, const float* gaddr, unsigned sz)
{
    asm volatile("cp.async.cg.shared.global [%0], [%1], 16, %2;\n"
                 :: "r"(saddr), "l"(gaddr), "r"(sz) : "memory");
}
__device__ __forceinline__ void cp_commit()
{
    asm volatile("cp.async.commit_group;\n" ::: "memory");
}

__global__ __launch_bounds__(NTHR, 4)
void la_kernel(const float* __restrict__ x,
               const float* __restrict__ kern,
               float* __restrict__ out)
{
    // ===================== EDGE BLOCKS (by == 32): pixels col 0,1 =====================
    if (blockIdx.y == 32) {
        const int tid = threadIdx.x;
        const int b   = blockIdx.z;
        const int R   = blockIdx.x * 64 + (tid >> 1);   // row 0..255
        const int col = tid & 1;                         // 0 or 1
        const float* xb = x + (long)b * NC * HW;

        float sc[K2];
        #pragma unroll
        for (int k = 0; k < K2; ++k) sc[k] = 0.0f;

        for (int ch = DYN; ch < NC; ++ch) {
            const float* cp = xb + ch * HW;
            float4 rowv[KS];
            #pragma unroll
            for (int i = 0; i < KS; ++i) {
                const int gr = R - 2 + i;
                rowv[i] = ((unsigned)gr < NH) ? *(const float4*)(cp + gr * NW)
                                              : make_float4(0.f, 0.f, 0.f, 0.f);
            }
            const float v = (col == 0) ? rowv[2].x : rowv[2].y;
            #pragma unroll
            for (int i = 0; i < KS; ++i) {
                if (col == 0) {
                    sc[i * KS + 2] = fmaf(rowv[i].x, v, sc[i * KS + 2]);
                    sc[i * KS + 3] = fmaf(rowv[i].y, v, sc[i * KS + 3]);
                    sc[i * KS + 4] = fmaf(rowv[i].z, v, sc[i * KS + 4]);
                } else {
                    sc[i * KS + 1] = fmaf(rowv[i].x, v, sc[i * KS + 1]);
                    sc[i * KS + 2] = fmaf(rowv[i].y, v, sc[i * KS + 2]);
                    sc[i * KS + 3] = fmaf(rowv[i].z, v, sc[i * KS + 3]);
                    sc[i * KS + 4] = fmaf(rowv[i].w, v, sc[i * KS + 4]);
                }
            }
        }
        // softmax (taps off the left edge keep score 0, matching zero padding)
        {
            float tmp[K2];
            #pragma unroll
            for (int k = 0; k < K2; ++k) tmp[k] = sc[k] * (__ldg(kern + k) * 0.2f);
            float m2 = tmp[0];
            #pragma unroll
            for (int k = 1; k < K2; ++k) m2 = fmaxf(m2, tmp[k]);
            float sum = 0.0f;
            #pragma unroll
            for (int k = 0; k < K2; ++k) { tmp[k] = __expf(tmp[k] - m2); sum += tmp[k]; }
            const float inv = 1.0f / sum;
            #pragma unroll
            for (int k = 0; k < K2; ++k) sc[k] = tmp[k] * inv;
        }
        // weighted sum over dynamic channels
        for (int ch = 0; ch < DYN; ++ch) {
            const float* cp = xb + ch * HW;
            float acc = 0.0f;
            #pragma unroll
            for (int i = 0; i < KS; ++i) {
                const int gr = R - 2 + i;
                const float4 rv = ((unsigned)gr < NH) ? *(const float4*)(cp + gr * NW)
                                                      : make_float4(0.f, 0.f, 0.f, 0.f);
                if (col == 0) {
                    acc = fmaf(sc[i * KS + 2], rv.x, acc);
                    acc = fmaf(sc[i * KS + 3], rv.y, acc);
                    acc = fmaf(sc[i * KS + 4], rv.z, acc);
                } else {
                    acc = fmaf(sc[i * KS + 1], rv.x, acc);
                    acc = fmaf(sc[i * KS + 2], rv.y, acc);
                    acc = fmaf(sc[i * KS + 3], rv.z, acc);
                    acc = fmaf(sc[i * KS + 4], rv.w, acc);
                }
            }
            out[((long)(b * DYN + ch) * NH + R) * NW + col] = acc;
        }
        return;
    }

    // ===================== MAIN BLOCKS =====================
    extern __shared__ __align__(16) unsigned char dynsm[];
    float4* smbuf = (float4*)dynsm;                          // [BUFS][F4_CK]
    int*    sgoff = (int*)(dynsm + (size_t)BUFS * F4_CK * 16);  // [NSLOT][NTHR]
    float*  skw   = (float*)(sgoff + NSLOT * NTHR);          // [K2]

    const int tid = threadIdx.x;
    const int tx  = tid & 15;
    const int ty  = tid >> 4;
    const int w0  = blockIdx.x * TW;
    const int h0  = blockIdx.y * TH;
    const int b   = blockIdx.z;
    const int ph  = h0 + ty;
    const int p0  = w0 + 2 + tx * PW;         // first owned pixel (shifted by +2)

    if (tid < K2) skw[tid] = kern[tid] * (1.0f / KS);

    // ---- chunk-invariant fill descriptors (16B granules), tile origin (w0, h0-2) ----
    #pragma unroll
    for (int s = 0; s < NSLOT; ++s) {
        const int e   = tid + s * NTHR;
        const int ch  = e / F4_CH;
        const int rem = e - ch * F4_CH;
        const int r   = rem / (SW / 4);
        const int j   = rem - r * (SW / 4);
        const int gh  = h0 - 2 + r;
        const int gw0 = w0 + j * 4;
        const bool ok = ((unsigned)gh < NH) && ((unsigned)gw0 < NW);
        sgoff[s * NTHR + tid] = ok ? (ch * HW + gh * NW + gw0) : -1;
    }
    __syncthreads();

    const float* xb = x + (long)b * NC * HW;

    // ---- prologue: issue chunks 0 and 1 ----
    #pragma unroll
    for (int pre = 0; pre < 2; ++pre) {
        const int cb = 32 + 4 * pre;          // static channels start at 32
        const float* g = xb + cb * HW;
        const uint32_t sb = (uint32_t)__cvta_generic_to_shared(&smbuf[(size_t)pre * F4_CK]);
        #pragma unroll
        for (int s = 0; s < NSLOT; ++s) {
            const int e = tid + s * NTHR;
            if (s < NSLOT - 1 || e < F4_CK) {
                const int off = sgoff[s * NTHR + tid];
                cp_async16(sb + (uint32_t)e * 16u, g + (off >= 0 ? off : 0),
                           off >= 0 ? 16u : 0u);
            }
        }
        cp_commit();
    }

    float sc[PW][K2];
    #pragma unroll
    for (int p = 0; p < PW; ++p)
        #pragma unroll
        for (int k = 0; k < K2; ++k) sc[p][k] = 0.0f;

    float inv[PW];

    for (int i = 0; i < NCHUNK; ++i) {
        // issue chunk i+2 (distance-2 prefetch)
        if (i + 2 < NCHUNK) {
            const int cn = i + 2;
            const int cb = (cn < 8) ? (32 + 4 * cn) : (4 * (cn - 8));
            const float* g = xb + cb * HW;
            const uint32_t sb = (uint32_t)__cvta_generic_to_shared(&smbuf[(size_t)(cn % BUFS) * F4_CK]);
            #pragma unroll
            for (int s = 0; s < NSLOT; ++s) {
                const int e = tid + s * NTHR;
                if (s < NSLOT - 1 || e < F4_CK) {
                    const int off = sgoff[s * NTHR + tid];
                    cp_async16(sb + (uint32_t)e * 16u, g + (off >= 0 ? off : 0),
                               off >= 0 ? 16u : 0u);
                }
            }
            cp_commit();
            asm volatile("cp.async.wait_group 2;\n" ::: "memory");
        } else if (i + 2 == NCHUNK) {
            asm volatile("cp.async.wait_group 1;\n" ::: "memory");
        } else {
            asm volatile("cp.async.wait_group 0;\n" ::: "memory");
        }
        __syncthreads();

        const float* buf = (const float*)&smbuf[(size_t)(i % BUFS) * F4_CK];

        if (i < 8) {
            // ================= Phase A: scores =================
            #pragma unroll
            for (int cc = 0; cc < CHK; ++cc) {
                const float* chb = buf + cc * (SH * SW) + ty * SW + tx * 4;
                float v[PW];
                {   // row r=2: strip supplies taps AND the 4 center values (s[2+p])
                    const float4 A = *(const float4*)(chb + 2 * SW);
                    const float4 B = *(const float4*)(chb + 2 * SW + 4);
                    v[0] = A.z; v[1] = A.w; v[2] = B.x; v[3] = B.y;
                    const float s[8] = {A.x, A.y, A.z, A.w, B.x, B.y, B.z, B.w};
                    #pragma unroll
                    for (int j = 0; j < KS; ++j)
                        #pragma unroll
                        for (int p = 0; p < PW; ++p)
                            sc[p][10 + j] = fmaf(s[j + p], v[p], sc[p][10 + j]);
                }
                #pragma unroll
                for (int rr = 0; rr < 4; ++rr) {
                    const int r = (rr < 2) ? rr : rr + 1;   // 0,1,3,4
                    const float4 A = *(const float4*)(chb + r * SW);
                    const float4 B = *(const float4*)(chb + r * SW + 4);
                    const float s[8] = {A.x, A.y, A.z, A.w, B.x, B.y, B.z, B.w};
                    #pragma unroll
                    for (int j = 0; j < KS; ++j)
                        #pragma unroll
                        for (int p = 0; p < PW; ++p)
                            sc[p][r * KS + j] = fmaf(s[j + p], v[p], sc[p][r * KS + j]);
                }
            }
            if (i == 7) {
                // ================= Phase B: softmax =================
                #pragma unroll
                for (int k = 0; k < K2; ++k) {
                    const float kw = skw[k];
                    #pragma unroll
                    for (int p = 0; p < PW; ++p) sc[p][k] *= kw;
                }
                #pragma unroll
                for (int p = 0; p < PW; ++p) {
                    float mx = sc[p][0];
                    #pragma unroll
                    for (int k = 1; k < K2; ++k) mx = fmaxf(mx, sc[p][k]);
                    float sum = 0.0f;
                    #pragma unroll
                    for (int k = 0; k < K2; ++k) {
                        const float e = __expf(sc[p][k] - mx);
                        sc[p][k] = e;
                        sum += e;
                    }
                    inv[p] = 1.0f / sum;
                }
            }
        } else {
            // ================= Phase C: weighted sum =================
            #pragma unroll
            for (int cc = 0; cc < CHK; ++cc) {
                const float* chb = buf + cc * (SH * SW) + ty * SW + tx * 4;
                float acc[PW] = {0.f, 0.f, 0.f, 0.f};
                #pragma unroll
                for (int r = 0; r < KS; ++r) {
                    const float4 A = *(const float4*)(chb + r * SW);
                    const float4 B = *(const float4*)(chb + r * SW + 4);
                    const float s[8] = {A.x, A.y, A.z, A.w, B.x, B.y, B.z, B.w};
                    #pragma unroll
                    for (int j = 0; j < KS; ++j)
                        #pragma unroll
                        for (int p = 0; p < PW; ++p)
                            acc[p] = fmaf(sc[p][r * KS + j], s[j + p], acc[p]);
                }
                const int c = (i - 8) * CHK + cc;
                float* op = &out[(((long)b * DYN + c) * NH + ph) * NW + p0];
                float2 o0 = make_float2(acc[0] * inv[0], acc[1] * inv[1]);
                *(float2*)op = o0;                       // pixels p0, p0+1 (always valid)
                if (p0 + 2 < NW) {                        // masked for bx=3, tx=15
                    float2 o1 = make_float2(acc[2] * inv[2], acc[3] * inv[3]);
                    *(float2*)(op + 2) = o1;
                }
            }
        }
    }
}

extern "C" void kernel_launch(void* const* d_in, const int* in_sizes, int n_in,
                              void* d_out, int out_size)
{
    const float* x    = (const float*)d_in[0];
    const float* kern = (const float*)d_in[1];
    float* out        = (float*)d_out;
    (void)in_sizes; (void)n_in; (void)out_size;

    static bool attr_set = false;
    if (!attr_set) {
        cudaFuncSetAttribute(la_kernel, cudaFuncAttributeMaxDynamicSharedMemorySize,
                             SMEM_BYTES);
        attr_set = true;
    }

    dim3 grid(NW / TW, NH / TH + 1, NB);   // (4, 33, 4): by==32 -> edge blocks
    dim3 block(NTHR);
    la_kernel<<<grid, block, SMEM_BYTES>>>(x, kern, out);
}

// round 11
// speedup vs baseline: 1.4958x; 1.0015x over previous
#include <cuda_runtime.h>
#include <cstdint>

#define KS     5
#define K2     25
#define DYN    32
#define NB     4
#define NC     64
#define NH     256
#define NW     256
#define HW     (NH*NW)

#define TW     64
#define TH     8
#define PW     4
#define SW     68                 // tile cols w0 .. w0+67 (origin w0, 16B aligned)
#define SH     12                 // rows h0-2 .. h0+9
#define CHK    4                  // channels per chunk
#define F4_CH  (SH*(SW/4))        // 204 float4 per channel
#define F4_CK  (CHK*F4_CH)        // 816 float4 per chunk
#define NSLOT  7                  // ceil(816/128)
#define NTHR   128
#define NCHUNK 16                 // 8 static + 8 dynamic
#define BUFS   4

#define SMEM_BYTES (BUFS*F4_CK*16 + NSLOT*NTHR*4 + K2*4)

__device__ __forceinline__ void cp_async16(uint32_t saddr, const float* gaddr, unsigned sz)
{
    asm volatile("cp.async.cg.shared.global [%0], [%1], 16, %2;\n"
                 :: "r"(saddr), "l"(gaddr), "r"(sz) : "memory");
}
__device__ __forceinline__ void cp_commit()
{
    asm volatile("cp.async.commit_group;\n" ::: "memory");
}

__global__ __launch_bounds__(NTHR, 4)
void la_kernel(const float* __restrict__ x,
               const float* __restrict__ kern,
               float* __restrict__ out)
{
    // ===================== EDGE BLOCKS (by == 32): pixels col 0,1 =====================
    if (blockIdx.y == 32) {
        const int tid = threadIdx.x;
        const int b   = blockIdx.z;
        const int R   = blockIdx.x * 64 + (tid >> 1);   // row 0..255
        const int col = tid & 1;                         // 0 or 1
        const float* xb = x + (long)b * NC * HW;

        float sc[K2];
        #pragma unroll
        for (int k = 0; k < K2; ++k) sc[k] = 0.0f;

        for (int ch = DYN; ch < NC; ++ch) {
            const float* cp = xb + ch * HW;
            float4 rowv[KS];
            #pragma unroll
            for (int i = 0; i < KS; ++i) {
                const int gr = R - 2 + i;
                rowv[i] = ((unsigned)gr < NH) ? *(const float4*)(cp + gr * NW)
                                              : make_float4(0.f, 0.f, 0.f, 0.f);
            }
            const float v = (col == 0) ? rowv[2].x : rowv[2].y;
            #pragma unroll
            for (int i = 0; i < KS; ++i) {
                if (col == 0) {
                    sc[i * KS + 2] = fmaf(rowv[i].x, v, sc[i * KS + 2]);
                    sc[i * KS + 3] = fmaf(rowv[i].y, v, sc[i * KS + 3]);
                    sc[i * KS + 4] = fmaf(rowv[i].z, v, sc[i * KS + 4]);
                } else {
                    sc[i * KS + 1] = fmaf(rowv[i].x, v, sc[i * KS + 1]);
                    sc[i * KS + 2] = fmaf(rowv[i].y, v, sc[i * KS + 2]);
                    sc[i * KS + 3] = fmaf(rowv[i].z, v, sc[i * KS + 3]);
                    sc[i * KS + 4] = fmaf(rowv[i].w, v, sc[i * KS + 4]);
                }
            }
        }
        // softmax (taps off the left edge keep score 0, matching zero padding)
        {
            float tmp[K2];
            #pragma unroll
            for (int k = 0; k < K2; ++k) tmp[k] = sc[k] * (__ldg(kern + k) * 0.2f);
            float m2 = tmp[0];
            #pragma unroll
            for (int k = 1; k < K2; ++k) m2 = fmaxf(m2, tmp[k]);
            float sum = 0.0f;
            #pragma unroll
            for (int k = 0; k < K2; ++k) { tmp[k] = __expf(tmp[k] - m2); sum += tmp[k]; }
            const float inv = 1.0f / sum;
            #pragma unroll
            for (int k = 0; k < K2; ++k) sc[k] = tmp[k] * inv;
        }
        // weighted sum over dynamic channels
        for (int ch = 0; ch < DYN; ++ch) {
            const float* cp = xb + ch * HW;
            float acc = 0.0f;
            #pragma unroll
            for (int i = 0; i < KS; ++i) {
                const int gr = R - 2 + i;
                const float4 rv = ((unsigned)gr < NH) ? *(const float4*)(cp + gr * NW)
                                                      : make_float4(0.f, 0.f, 0.f, 0.f);
                if (col == 0) {
                    acc = fmaf(sc[i * KS + 2], rv.x, acc);
                    acc = fmaf(sc[i * KS + 3], rv.y, acc);
                    acc = fmaf(sc[i * KS + 4], rv.z, acc);
                } else {
                    acc = fmaf(sc[i * KS + 1], rv.x, acc);
                    acc = fmaf(sc[i * KS + 2], rv.y, acc);
                    acc = fmaf(sc[i * KS + 3], rv.z, acc);
                    acc = fmaf(sc[i * KS + 4], rv.w, acc);
                }
            }
            out[((long)(b * DYN + ch) * NH + R) * NW + col] = acc;
        }
        return;
    }

    // ===================== MAIN BLOCKS =====================
    extern __shared__ __align__(16) unsigned char dynsm[];
    float4* smbuf = (float4*)dynsm;                             // [BUFS][F4_CK]
    int*    sgoff = (int*)(dynsm + (size_t)BUFS * F4_CK * 16);  // [NSLOT][NTHR]
    float*  skw   = (float*)(sgoff + NSLOT * NTHR);             // [K2]

    const int tid = threadIdx.x;
    const int tx  = tid & 15;
    const int ty  = tid >> 4;
    const int w0  = blockIdx.x * TW;
    const int h0  = blockIdx.y * TH;
    const int b   = blockIdx.z;
    const int ph  = h0 + ty;
    const int p0  = w0 + 2 + tx * PW;         // first owned pixel (shifted by +2)

    // fold log2(e)/KS into the tap weights -> exp2f in softmax (saves the FMUL)
    if (tid < K2) skw[tid] = kern[tid] * (1.4426950408889634f / KS);

    // ---- chunk-invariant fill descriptors; each thread reads only its own rows ----
    #pragma unroll
    for (int s = 0; s < NSLOT; ++s) {
        const int e   = tid + s * NTHR;
        const int ch  = e / F4_CH;
        const int rem = e - ch * F4_CH;
        const int r   = rem / (SW / 4);
        const int j   = rem - r * (SW / 4);
        const int gh  = h0 - 2 + r;
        const int gw0 = w0 + j * 4;
        const bool ok = ((unsigned)gh < NH) && ((unsigned)gw0 < NW);
        sgoff[s * NTHR + tid] = ok ? (ch * HW + gh * NW + gw0) : -1;
    }

    const float* xb = x + (long)b * NC * HW;

    // ---- prologue: issue chunks 0, 1 ----
    #pragma unroll
    for (int pre = 0; pre < 2; ++pre) {
        const float* g = xb + (32 + 4 * pre) * HW;
        const uint32_t sb = (uint32_t)__cvta_generic_to_shared(&smbuf[(size_t)pre * F4_CK]);
        #pragma unroll
        for (int s = 0; s < NSLOT; ++s) {
            const int e = tid + s * NTHR;
            if (s < NSLOT - 1 || e < F4_CK) {
                const int off = sgoff[s * NTHR + tid];
                cp_async16(sb + (uint32_t)e * 16u, g + (off >= 0 ? off : 0),
                           off >= 0 ? 16u : 0u);
            }
        }
        cp_commit();
    }

    float sc[PW][K2];
    #pragma unroll
    for (int p = 0; p < PW; ++p)
        #pragma unroll
        for (int k = 0; k < K2; ++k) sc[p][k] = 0.0f;

    float inv[PW];

    for (int s2 = 0; s2 < NCHUNK / 2; ++s2) {
        // all outstanding groups done => chunks 2s2, 2s2+1 resident
        asm volatile("cp.async.wait_group 0;\n" ::: "memory");
        __syncthreads();

        // issue chunks 2s2+2, 2s2+3 (buffers last read in super-iter s2-1)
        if (s2 + 1 < NCHUNK / 2) {
            #pragma unroll
            for (int q = 0; q < 2; ++q) {
                const int cn = 2 * s2 + 2 + q;
                const int cb = (cn < 8) ? (32 + 4 * cn) : (4 * (cn - 8));
                const float* g = xb + cb * HW;
                const uint32_t sb = (uint32_t)__cvta_generic_to_shared(
                    &smbuf[(size_t)(cn % BUFS) * F4_CK]);
                #pragma unroll
                for (int s = 0; s < NSLOT; ++s) {
                    const int e = tid + s * NTHR;
                    if (s < NSLOT - 1 || e < F4_CK) {
                        const int off = sgoff[s * NTHR + tid];
                        cp_async16(sb + (uint32_t)e * 16u, g + (off >= 0 ? off : 0),
                                   off >= 0 ? 16u : 0u);
                    }
                }
                cp_commit();
            }
        }

        // ---- compute the two resident chunks, barrier-free ----
        #pragma unroll
        for (int h = 0; h < 2; ++h) {
            const int i = 2 * s2 + h;
            const float* buf = (const float*)&smbuf[(size_t)(i % BUFS) * F4_CK];

            if (i < 8) {
                // ================= Phase A: scores =================
                #pragma unroll
                for (int cc = 0; cc < CHK; ++cc) {
                    const float* chb = buf + cc * (SH * SW) + ty * SW + tx * 4;
                    float v[PW];
                    {   // row r=2: strip supplies taps AND the 4 center values
                        const float4 A = *(const float4*)(chb + 2 * SW);
                        const float4 B = *(const float4*)(chb + 2 * SW + 4);
                        v[0] = A.z; v[1] = A.w; v[2] = B.x; v[3] = B.y;
                        const float s[8] = {A.x, A.y, A.z, A.w, B.x, B.y, B.z, B.w};
                        #pragma unroll
                        for (int j = 0; j < KS; ++j)
                            #pragma unroll
                            for (int p = 0; p < PW; ++p)
                                sc[p][10 + j] = fmaf(s[j + p], v[p], sc[p][10 + j]);
                    }
                    #pragma unroll
                    for (int rr = 0; rr < 4; ++rr) {
                        const int r = (rr < 2) ? rr : rr + 1;   // 0,1,3,4
                        const float4 A = *(const float4*)(chb + r * SW);
                        const float4 B = *(const float4*)(chb + r * SW + 4);
                        const float s[8] = {A.x, A.y, A.z, A.w, B.x, B.y, B.z, B.w};
                        #pragma unroll
                        for (int j = 0; j < KS; ++j)
                            #pragma unroll
                            for (int p = 0; p < PW; ++p)
                                sc[p][r * KS + j] = fmaf(s[j + p], v[p], sc[p][r * KS + j]);
                    }
                }
                if (i == 7) {
                    // ================= Phase B: softmax (log2 domain) =================
                    #pragma unroll
                    for (int k = 0; k < K2; ++k) {
                        const float kw = skw[k];
                        #pragma unroll
                        for (int p = 0; p < PW; ++p) sc[p][k] *= kw;
                    }
                    #pragma unroll
                    for (int p = 0; p < PW; ++p) {
                        float mx = sc[p][0];
                        #pragma unroll
                        for (int k = 1; k < K2; ++k) mx = fmaxf(mx, sc[p][k]);
                        float sum = 0.0f;
                        #pragma unroll
                        for (int k = 0; k < K2; ++k) {
                            const float e = exp2f(sc[p][k] - mx);
                            sc[p][k] = e;
                            sum += e;
                        }
                        inv[p] = 1.0f / sum;
                    }
                }
            } else {
                // ================= Phase C: weighted sum =================
                #pragma unroll
                for (int cc = 0; cc < CHK; ++cc) {
                    const float* chb = buf + cc * (SH * SW) + ty * SW + tx * 4;
                    float acc[PW] = {0.f, 0.f, 0.f, 0.f};
                    #pragma unroll
                    for (int r = 0; r < KS; ++r) {
                        const float4 A = *(const float4*)(chb + r * SW);
                        const float4 B = *(const float4*)(chb + r * SW + 4);
                        const float s[8] = {A.x, A.y, A.z, A.w, B.x, B.y, B.z, B.w};
                        #pragma unroll
                        for (int j = 0; j < KS; ++j)
                            #pragma unroll
                            for (int p = 0; p < PW; ++p)
                                acc[p] = fmaf(sc[p][r * KS + j], s[j + p], acc[p]);
                    }
                    const int c = (i - 8) * CHK + cc;
                    float* op = &out[(((long)b * DYN + c) * NH + ph) * NW + p0];
                    float2 o0 = make_float2(acc[0] * inv[0], acc[1] * inv[1]);
                    *(float2*)op = o0;                       // pixels p0, p0+1
                    if (p0 + 2 < NW) {                        // masked for bx=3, tx=15
                        float2 o1 = make_float2(acc[2] * inv[2], acc[3] * inv[3]);
                        *(float2*)(op + 2) = o1;
                    }
                }
            }
        }
    }
}

extern "C" void kernel_launch(void* const* d_in, const int* in_sizes, int n_in,
                              void* d_out, int out_size)
{
    const float* x    = (const float*)d_in[0];
    const float* kern = (const float*)d_in[1];
    float* out        = (float*)d_out;
    (void)in_sizes; (void)n_in; (void)out_size;

    static bool attr_set = false;
    if (!attr_set) {
        cudaFuncSetAttribute(la_kernel, cudaFuncAttributeMaxDynamicSharedMemorySize,
                             SMEM_BYTES);
        attr_set = true;
    }

    dim3 grid(NW / TW, NH / TH + 1, NB);   // (4, 33, 4): by==32 -> edge blocks
    dim3 block(NTHR);
    la_kernel<<<grid, block, SMEM_BYTES>>>(x, kern, out);
}

// round 12
// speedup vs baseline: 1.5646x; 1.0460x over previous
#include <cuda_runtime.h>
#include <cstdint>

#define KS     5
#define K2     25
#define DYN    32
#define NB     4
#define NC     64
#define NH     256
#define NW     256
#define HW     (NH*NW)

#define TW     32
#define TH     8
#define PW     4
#define SW     36                 // tile cols w0 .. w0+35 (origin w0, 16B aligned)
#define SH     12                 // rows h0-2 .. h0+9
#define CHK    4                  // channels per chunk
#define F4_CH  (SH*(SW/4))        // 108 float4 per channel
#define F4_CK  (CHK*F4_CH)        // 432 float4 per chunk
#define NSLOT  7                  // ceil(432/64)
#define NTHR   64
#define NCHUNK 16                 // 8 static + 8 dynamic
#define BUFS   3                  // distance-2 prefetch, barrier-guarded reuse

#define SMEM_BYTES (BUFS*F4_CK*16 + NSLOT*NTHR*4 + K2*4)

__device__ __forceinline__ void cp_async16(uint32_t saddr, const float* gaddr, unsigned sz)
{
    asm volatile("cp.async.cg.shared.global [%0], [%1], 16, %2;\n"
                 :: "r"(saddr), "l"(gaddr), "r"(sz) : "memory");
}
__device__ __forceinline__ void cp_commit()
{
    asm volatile("cp.async.commit_group;\n" ::: "memory");
}

__global__ __launch_bounds__(NTHR, 8)
void la_kernel(const float* __restrict__ x,
               const float* __restrict__ kern,
               float* __restrict__ out)
{
    // ===================== EDGE BLOCKS (by == 32): pixels col 0,1 =====================
    if (blockIdx.y == 32) {
        const int tid = threadIdx.x;
        const int b   = blockIdx.z;
        const int R   = blockIdx.x * 32 + (tid >> 1);   // row 0..255 (8 blocks x 32 rows)
        const int col = tid & 1;                         // 0 or 1
        const float* xb = x + (long)b * NC * HW;

        float sc[K2];
        #pragma unroll
        for (int k = 0; k < K2; ++k) sc[k] = 0.0f;

        for (int ch = DYN; ch < NC; ++ch) {
            const float* cp = xb + ch * HW;
            float4 rowv[KS];
            #pragma unroll
            for (int i = 0; i < KS; ++i) {
                const int gr = R - 2 + i;
                rowv[i] = ((unsigned)gr < NH) ? *(const float4*)(cp + gr * NW)
                                              : make_float4(0.f, 0.f, 0.f, 0.f);
            }
            const float v = (col == 0) ? rowv[2].x : rowv[2].y;
            #pragma unroll
            for (int i = 0; i < KS; ++i) {
                if (col == 0) {
                    sc[i * KS + 2] = fmaf(rowv[i].x, v, sc[i * KS + 2]);
                    sc[i * KS + 3] = fmaf(rowv[i].y, v, sc[i * KS + 3]);
                    sc[i * KS + 4] = fmaf(rowv[i].z, v, sc[i * KS + 4]);
                } else {
                    sc[i * KS + 1] = fmaf(rowv[i].x, v, sc[i * KS + 1]);
                    sc[i * KS + 2] = fmaf(rowv[i].y, v, sc[i * KS + 2]);
                    sc[i * KS + 3] = fmaf(rowv[i].z, v, sc[i * KS + 3]);
                    sc[i * KS + 4] = fmaf(rowv[i].w, v, sc[i * KS + 4]);
                }
            }
        }
        // softmax (taps off the left edge keep score 0, matching zero padding)
        {
            float tmp[K2];
            #pragma unroll
            for (int k = 0; k < K2; ++k) tmp[k] = sc[k] * (__ldg(kern + k) * 0.2f);
            float m2 = tmp[0];
            #pragma unroll
            for (int k = 1; k < K2; ++k) m2 = fmaxf(m2, tmp[k]);
            float sum = 0.0f;
            #pragma unroll
            for (int k = 0; k < K2; ++k) { tmp[k] = __expf(tmp[k] - m2); sum += tmp[k]; }
            const float inv = 1.0f / sum;
            #pragma unroll
            for (int k = 0; k < K2; ++k) sc[k] = tmp[k] * inv;
        }
        // weighted sum over dynamic channels
        for (int ch = 0; ch < DYN; ++ch) {
            const float* cp = xb + ch * HW;
            float acc = 0.0f;
            #pragma unroll
            for (int i = 0; i < KS; ++i) {
                const int gr = R - 2 + i;
                const float4 rv = ((unsigned)gr < NH) ? *(const float4*)(cp + gr * NW)
                                                      : make_float4(0.f, 0.f, 0.f, 0.f);
                if (col == 0) {
                    acc = fmaf(sc[i * KS + 2], rv.x, acc);
                    acc = fmaf(sc[i * KS + 3], rv.y, acc);
                    acc = fmaf(sc[i * KS + 4], rv.z, acc);
                } else {
                    acc = fmaf(sc[i * KS + 1], rv.x, acc);
                    acc = fmaf(sc[i * KS + 2], rv.y, acc);
                    acc = fmaf(sc[i * KS + 3], rv.z, acc);
                    acc = fmaf(sc[i * KS + 4], rv.w, acc);
                }
            }
            out[((long)(b * DYN + ch) * NH + R) * NW + col] = acc;
        }
        return;
    }

    // ===================== MAIN BLOCKS =====================
    extern __shared__ __align__(16) unsigned char dynsm[];
    float4* smbuf = (float4*)dynsm;                             // [BUFS][F4_CK]
    int*    sgoff = (int*)(dynsm + (size_t)BUFS * F4_CK * 16);  // [NSLOT][NTHR]
    float*  skw   = (float*)(sgoff + NSLOT * NTHR);             // [K2]

    const int tid = threadIdx.x;
    const int tx  = tid & 7;                  // 0..7
    const int ty  = tid >> 3;                 // 0..7
    const int w0  = blockIdx.x * TW;
    const int h0  = blockIdx.y * TH;
    const int b   = blockIdx.z;
    const int ph  = h0 + ty;
    const int p0  = w0 + 2 + tx * PW;         // first owned pixel (shifted by +2)

    // fold log2(e)/KS into tap weights -> exp2f softmax
    if (tid < K2) skw[tid] = kern[tid] * (1.4426950408889634f / KS);

    // ---- chunk-invariant fill descriptors; each thread reads only its own rows ----
    #pragma unroll
    for (int s = 0; s < NSLOT; ++s) {
        const int e   = tid + s * NTHR;
        const int ch  = e / F4_CH;
        const int rem = e - ch * F4_CH;
        const int r   = rem / (SW / 4);
        const int j   = rem - r * (SW / 4);
        const int gh  = h0 - 2 + r;
        const int gw0 = w0 + j * 4;
        const bool ok = ((unsigned)gh < NH) && ((unsigned)gw0 < NW);
        sgoff[s * NTHR + tid] = ok ? (ch * HW + gh * NW + gw0) : -1;
    }

    const float* xb = x + (long)b * NC * HW;

    // ---- prologue: issue chunks 0, 1 ----
    #pragma unroll
    for (int pre = 0; pre < 2; ++pre) {
        const float* g = xb + (32 + 4 * pre) * HW;
        const uint32_t sb = (uint32_t)__cvta_generic_to_shared(&smbuf[(size_t)pre * F4_CK]);
        #pragma unroll
        for (int s = 0; s < NSLOT; ++s) {
            const int e = tid + s * NTHR;
            if (s < NSLOT - 1 || e < F4_CK) {
                const int off = sgoff[s * NTHR + tid];
                cp_async16(sb + (uint32_t)e * 16u, g + (off >= 0 ? off : 0),
                           off >= 0 ? 16u : 0u);
            }
        }
        cp_commit();
    }

    float sc[PW][K2];
    #pragma unroll
    for (int p = 0; p < PW; ++p)
        #pragma unroll
        for (int k = 0; k < K2; ++k) sc[p][k] = 0.0f;

    float inv[PW];

    for (int i = 0; i < NCHUNK; ++i) {
        // issue chunk i+2 (distance-2); buffer (i+2)%3 last read at iter i-1,
        // protected by this iteration's barrier below issued AFTER wait.
        if (i + 2 < NCHUNK) {
            const int cn = i + 2;
            const int cb = (cn < 8) ? (32 + 4 * cn) : (4 * (cn - 8));
            const float* g = xb + cb * HW;
            const uint32_t sb = (uint32_t)__cvta_generic_to_shared(
                &smbuf[(size_t)(cn % BUFS) * F4_CK]);
            #pragma unroll
            for (int s = 0; s < NSLOT; ++s) {
                const int e = tid + s * NTHR;
                if (s < NSLOT - 1 || e < F4_CK) {
                    const int off = sgoff[s * NTHR + tid];
                    cp_async16(sb + (uint32_t)e * 16u, g + (off >= 0 ? off : 0),
                               off >= 0 ? 16u : 0u);
                }
            }
            cp_commit();
            asm volatile("cp.async.wait_group 2;\n" ::: "memory");
        } else if (i + 2 == NCHUNK) {
            asm volatile("cp.async.wait_group 1;\n" ::: "memory");
        } else {
            asm volatile("cp.async.wait_group 0;\n" ::: "memory");
        }
        __syncthreads();

        const float* buf = (const float*)&smbuf[(size_t)(i % BUFS) * F4_CK];

        if (i < 8) {
            // ================= Phase A: scores =================
            #pragma unroll
            for (int cc = 0; cc < CHK; ++cc) {
                const float* chb = buf + cc * (SH * SW) + ty * SW + tx * 4;
                float v[PW];
                {   // row r=2: strip supplies taps AND the 4 center values
                    const float4 A = *(const float4*)(chb + 2 * SW);
                    const float4 B = *(const float4*)(chb + 2 * SW + 4);
                    v[0] = A.z; v[1] = A.w; v[2] = B.x; v[3] = B.y;
                    const float s[8] = {A.x, A.y, A.z, A.w, B.x, B.y, B.z, B.w};
                    #pragma unroll
                    for (int j = 0; j < KS; ++j)
                        #pragma unroll
                        for (int p = 0; p < PW; ++p)
                            sc[p][10 + j] = fmaf(s[j + p], v[p], sc[p][10 + j]);
                }
                #pragma unroll
                for (int rr = 0; rr < 4; ++rr) {
                    const int r = (rr < 2) ? rr : rr + 1;   // 0,1,3,4
                    const float4 A = *(const float4*)(chb + r * SW);
                    const float4 B = *(const float4*)(chb + r * SW + 4);
                    const float s[8] = {A.x, A.y, A.z, A.w, B.x, B.y, B.z, B.w};
                    #pragma unroll
                    for (int j = 0; j < KS; ++j)
                        #pragma unroll
                        for (int p = 0; p < PW; ++p)
                            sc[p][r * KS + j] = fmaf(s[j + p], v[p], sc[p][r * KS + j]);
                }
            }
            if (i == 7) {
                // ================= Phase B: softmax (log2 domain) =================
                #pragma unroll
                for (int k = 0; k < K2; ++k) {
                    const float kw = skw[k];
                    #pragma unroll
                    for (int p = 0; p < PW; ++p) sc[p][k] *= kw;
                }
                #pragma unroll
                for (int p = 0; p < PW; ++p) {
                    float mx = sc[p][0];
                    #pragma unroll
                    for (int k = 1; k < K2; ++k) mx = fmaxf(mx, sc[p][k]);
                    float sum = 0.0f;
                    #pragma unroll
                    for (int k = 0; k < K2; ++k) {
                        const float e = exp2f(sc[p][k] - mx);
                        sc[p][k] = e;
                        sum += e;
                    }
                    inv[p] = 1.0f / sum;
                }
            }
        } else {
            // ================= Phase C: weighted sum =================
            #pragma unroll
            for (int cc = 0; cc < CHK; ++cc) {
                const float* chb = buf + cc * (SH * SW) + ty * SW + tx * 4;
                float acc[PW] = {0.f, 0.f, 0.f, 0.f};
                #pragma unroll
                for (int r = 0; r < KS; ++r) {
                    const float4 A = *(const float4*)(chb + r * SW);
                    const float4 B = *(const float4*)(chb + r * SW + 4);
                    const float s[8] = {A.x, A.y, A.z, A.w, B.x, B.y, B.z, B.w};
                    #pragma unroll
                    for (int j = 0; j < KS; ++j)
                        #pragma unroll
                        for (int p = 0; p < PW; ++p)
                            acc[p] = fmaf(sc[p][r * KS + j], s[j + p], acc[p]);
                }
                const int c = (i - 8) * CHK + cc;
                float* op = &out[(((long)b * DYN + c) * NH + ph) * NW + p0];
                float2 o0 = make_float2(acc[0] * inv[0], acc[1] * inv[1]);
                *(float2*)op = o0;                       // pixels p0, p0+1
                if (p0 + 2 < NW) {                        // masked for last block, tx=7
                    float2 o1 = make_float2(acc[2] * inv[2], acc[3] * inv[3]);
                    *(float2*)(op + 2) = o1;
                }
            }
        }
    }
}

extern "C" void kernel_launch(void* const* d_in, const int* in_sizes, int n_in,
                              void* d_out, int out_size)
{
    const float* x    = (const float*)d_in[0];
    const float* kern = (const float*)d_in[1];
    float* out        = (float*)d_out;
    (void)in_sizes; (void)n_in; (void)out_size;

    static bool attr_set = false;
    if (!attr_set) {
        cudaFuncSetAttribute(la_kernel, cudaFuncAttributeMaxDynamicSharedMemorySize,
                             SMEM_BYTES);
        attr_set = true;
    }

    dim3 grid(NW / TW, NH / TH + 1, NB);   // (8, 33, 4): by==32 -> edge blocks
    dim3 block(NTHR);
    la_kernel<<<grid, block, SMEM_BYTES>>>(x, kern, out);
}